// round 16
// baseline (speedup 1.0000x reference)
#include <cuda_runtime.h>

typedef unsigned long long ull;

#define B_ 2048
#define T_ 128
#define D_ 128
#define H_ 64
#define G_ 256   // 4*H

// 128 MB scratch for XZ1, layout [t][b][g]
__device__ float g_xz1[(size_t)T_ * B_ * G_];

// ---------------- f32x2 helpers ----------------
__device__ __forceinline__ ull splat2(float v) {
    ull r; asm("mov.b64 %0,{%1,%1};" : "=l"(r) : "f"(v)); return r;
}
__device__ __forceinline__ ull pack2(float lo, float hi) {
    ull r; asm("mov.b64 %0,{%1,%2};" : "=l"(r) : "f"(lo), "f"(hi)); return r;
}
__device__ __forceinline__ ull ffma2(ull a, ull b, ull c) {
    ull d; asm("fma.rn.f32x2 %0,%1,%2,%3;" : "=l"(d) : "l"(a), "l"(b), "l"(c)); return d;
}
__device__ __forceinline__ float2 unpack2(ull v) {
    float2 f; asm("mov.b64 {%0,%1},%2;" : "=f"(f.x), "=f"(f.y) : "l"(v)); return f;
}
__device__ __forceinline__ float foldz(ull v) {
    float2 f = unpack2(v); return f.x + f.y;
}
__device__ __forceinline__ float sigf(float x) {
    return __fdividef(1.f, 1.f + __expf(-x));
}
__device__ __forceinline__ float tanhf_(float x) {
    return 2.f * __fdividef(1.f, 1.f + __expf(-2.f * x)) - 1.f;
}

// ---------------------------------------------------------------------------
// Kernel 1: XZ1[t][b][g] = sum_d x[m][d] * W1[d][g] + b1[g]  (m = b*T + t)
// (unchanged — measured good)
// ---------------------------------------------------------------------------
#define GR 32
__global__ void __launch_bounds__(256) xz1_gemm_kernel(
    const float* __restrict__ x, const float* __restrict__ W1,
    const float* __restrict__ b1)
{
    __shared__ ull xp[D_ * 16];   // [d][pair], pair p = rows (p, p+16)
    const int tid = threadIdx.x;
    const int m0 = blockIdx.x * GR;

    const float4* xv = (const float4*)x;
    #pragma unroll
    for (int i = 0; i < 2; i++) {
        int u = tid + i * 256;
        int p = u >> 5, c4 = u & 31;
        float4 a = xv[(size_t)(m0 + p) * 32 + c4];
        float4 b = xv[(size_t)(m0 + p + 16) * 32 + c4];
        xp[(4 * c4 + 0) * 16 + p] = pack2(a.x, b.x);
        xp[(4 * c4 + 1) * 16 + p] = pack2(a.y, b.y);
        xp[(4 * c4 + 2) * 16 + p] = pack2(a.z, b.z);
        xp[(4 * c4 + 3) * 16 + p] = pack2(a.w, b.w);
    }
    __syncthreads();

    const int cp = tid & 127;
    const int rh = (tid >> 7) << 3;

    const float2 bias = *(const float2*)(b1 + 2 * cp);
    ull acc0[8], acc1[8];
    #pragma unroll
    for (int j = 0; j < 8; j++) { acc0[j] = splat2(bias.x); acc1[j] = splat2(bias.y); }

    const float2* Wp = (const float2*)W1 + cp;
    #pragma unroll 4
    for (int k = 0; k < D_; k++) {
        float2 w = Wp[k * 128];
        ull ws0 = splat2(w.x), ws1 = splat2(w.y);
        const ull* xr = xp + k * 16 + rh;
        ulonglong2 q0 = *(const ulonglong2*)(xr);
        ulonglong2 q1 = *(const ulonglong2*)(xr + 2);
        ulonglong2 q2 = *(const ulonglong2*)(xr + 4);
        ulonglong2 q3 = *(const ulonglong2*)(xr + 6);
        acc0[0] = ffma2(q0.x, ws0, acc0[0]); acc1[0] = ffma2(q0.x, ws1, acc1[0]);
        acc0[1] = ffma2(q0.y, ws0, acc0[1]); acc1[1] = ffma2(q0.y, ws1, acc1[1]);
        acc0[2] = ffma2(q1.x, ws0, acc0[2]); acc1[2] = ffma2(q1.x, ws1, acc1[2]);
        acc0[3] = ffma2(q1.y, ws0, acc0[3]); acc1[3] = ffma2(q1.y, ws1, acc1[3]);
        acc0[4] = ffma2(q2.x, ws0, acc0[4]); acc1[4] = ffma2(q2.x, ws1, acc1[4]);
        acc0[5] = ffma2(q2.y, ws0, acc0[5]); acc1[5] = ffma2(q2.y, ws1, acc1[5]);
        acc0[6] = ffma2(q3.x, ws0, acc0[6]); acc1[6] = ffma2(q3.x, ws1, acc1[6]);
        acc0[7] = ffma2(q3.y, ws0, acc0[7]); acc1[7] = ffma2(q3.y, ws1, acc1[7]);
    }

    #pragma unroll
    for (int j = 0; j < 8; j++) {
        float2 va = unpack2(acc0[j]);
        float2 vb = unpack2(acc1[j]);
        int m = m0 + rh + j;
        *(float2*)(g_xz1 + (size_t)(m & 127) * (B_ * G_)
                         + (size_t)(m >> 7) * G_ + 2 * cp) = make_float2(va.x, vb.x);
        m += 16;
        *(float2*)(g_xz1 + (size_t)(m & 127) * (B_ * G_)
                         + (size_t)(m >> 7) * G_ + 2 * cp) = make_float2(va.y, vb.y);
    }
}

// ---------------------------------------------------------------------------
// Kernel 2: fused persistent 2-layer LSTM scan, gate-quad, 512 threads.
// 128 CTAs x 512 threads (16 warps, occ 25%); CTA owns BT=16 batch rows.
// Warp covers 4 hidden units x 8 row-slots: lane = h_local*8 + rg.
// Thread = hidden unit h (4 gates) x rows {rg, rg+8}.
// h-state ping-pong ulonglong2 hh[2][16][HSTR]: .x = h1 K-pair, .y = h2 K-pair.
// ---------------------------------------------------------------------------
#define BT 16
#define HSTR 33
// smem: U1kp 64KB | WU2 128KB | hh 2 x 16 x 33 x 16B = 16896B  -> 213504B
#define SCAN_SMEM (65536 + 131072 + 2 * 16 * HSTR * 16)

__global__ void __launch_bounds__(512, 1) lstm_scan_kernel(
    const float* __restrict__ U1g, const float* __restrict__ W2g,
    const float* __restrict__ U2g, const float* __restrict__ b2g,
    float* __restrict__ out)
{
    extern __shared__ char smb[];
    ull* U1kp = (ull*)smb;                                   // [32][256]
    ulonglong2* WU2 = (ulonglong2*)(smb + 65536);            // [32][256] {W2pair, U2pair}
    ulonglong2* hh  = (ulonglong2*)(smb + 65536 + 131072);   // 2 x [16][HSTR]

    const int tid = threadIdx.x;
    const int lane = tid & 31;
    const int w = tid >> 5;
    const int h = w * 4 + (lane >> 3);    // 4 h per warp
    const int rg = lane & 7;              // rows rg, rg+8
    const int b0g = blockIdx.x * BT;

    for (int i = tid; i < 8192; i += 512) {
        int kk = i >> 8, gg = i & 255;
        U1kp[i] = pack2(U1g[(2 * kk) * G_ + gg], U1g[(2 * kk + 1) * G_ + gg]);
        WU2[i] = make_ulonglong2(
            pack2(W2g[(2 * kk) * G_ + gg], W2g[(2 * kk + 1) * G_ + gg]),
            pack2(U2g[(2 * kk) * G_ + gg], U2g[(2 * kk + 1) * G_ + gg]));
    }
    for (int i = tid; i < 2 * 16 * HSTR; i += 512) hh[i] = make_ulonglong2(0ull, 0ull);

    const float bb_i = b2g[h];
    const float bb_f = b2g[64 + h];
    const float bb_g = b2g[128 + h];
    const float bb_o = b2g[192 + h];

    const int hk = h >> 1;        // state kk slot
    const int hhalf = h & 1;      // float within pair

    float c1[2] = {0.f, 0.f};
    float c2[2] = {0.f, 0.f};
    __syncthreads();

    for (int t = 0; t < T_; t++) {
        ulonglong2* hrd = hh + (t & 1) * (16 * HSTR);
        ulonglong2* hwr = hh + ((t & 1) ^ 1) * (16 * HSTR);
        float* hwrf = (float*)hwr;

        // ---- phase A: z1 = XZ1 + h1_prev @ U1, gates in-register ----
        float xq[4][2];    // [gate][j]
        {
            const float* xp = g_xz1 + ((size_t)t * B_ + b0g + rg) * G_ + h;
            #pragma unroll
            for (int j = 0; j < 2; j++) {
                const float* xr = xp + (size_t)(8 * j) * G_;
                xq[0][j] = xr[0];
                xq[1][j] = xr[64];
                xq[2][j] = xr[128];
                xq[3][j] = xr[192];
            }
        }
        ull ai[2] = {0,0}, af[2] = {0,0}, ag[2] = {0,0}, ao[2] = {0,0};

        #pragma unroll 4
        for (int kk = 0; kk < 32; kk++) {
            ull ui = U1kp[kk * 256 + h];          // 4 distinct x 8-dup -> 1 wf
            ull uf = U1kp[kk * 256 + 64 + h];
            ull ug = U1kp[kk * 256 + 128 + h];
            ull uo = U1kp[kk * 256 + 192 + h];
            #pragma unroll
            for (int j = 0; j < 2; j++) {
                ull hv = hrd[(rg + 8 * j) * HSTR + kk].x;   // 8 rows, distinct banks
                ai[j] = ffma2(hv, ui, ai[j]);
                af[j] = ffma2(hv, uf, af[j]);
                ag[j] = ffma2(hv, ug, ag[j]);
                ao[j] = ffma2(hv, uo, ao[j]);
            }
        }
        #pragma unroll
        for (int j = 0; j < 2; j++) {
            float zi = xq[0][j] + foldz(ai[j]);
            float zf = xq[1][j] + foldz(af[j]);
            float zg = xq[2][j] + foldz(ag[j]);
            float zo = xq[3][j] + foldz(ao[j]);
            float iv = sigf(zi), fv = sigf(zf), gv = tanhf_(zg), ov = sigf(zo);
            c1[j] = fmaf(fv, c1[j], iv * gv);
            hwrf[((rg + 8 * j) * HSTR + hk) * 4 + hhalf] = ov * tanhf_(c1[j]);
        }
        __syncthreads();

        // ---- phase C: z2 = h1_new @ W2 + h2_prev @ U2 + b2 ----
        ull bi[2] = {0,0}, bf[2] = {0,0}, bg[2] = {0,0}, bo[2] = {0,0};

        #pragma unroll 4
        for (int kk = 0; kk < 32; kk++) {
            ulonglong2 qi = WU2[kk * 256 + h];        // 4 x 16B x 8-dup -> 1 wf
            ulonglong2 qf = WU2[kk * 256 + 64 + h];
            ulonglong2 qg = WU2[kk * 256 + 128 + h];
            ulonglong2 qo = WU2[kk * 256 + 192 + h];
            #pragma unroll
            for (int j = 0; j < 2; j++) {
                ull h1v = hwr[(rg + 8 * j) * HSTR + kk].x;   // h1_new
                ull h2v = hrd[(rg + 8 * j) * HSTR + kk].y;   // h2_prev
                bi[j] = ffma2(h1v, qi.x, ffma2(h2v, qi.y, bi[j]));
                bf[j] = ffma2(h1v, qf.x, ffma2(h2v, qf.y, bf[j]));
                bg[j] = ffma2(h1v, qg.x, ffma2(h2v, qg.y, bg[j]));
                bo[j] = ffma2(h1v, qo.x, ffma2(h2v, qo.y, bo[j]));
            }
        }
        #pragma unroll
        for (int j = 0; j < 2; j++) {
            float zi = bb_i + foldz(bi[j]);
            float zf = bb_f + foldz(bf[j]);
            float zg = bb_g + foldz(bg[j]);
            float zo = bb_o + foldz(bo[j]);
            float iv = sigf(zi), fv = sigf(zf), gv = sigf(zg), ov = sigf(zo);
            c2[j] = fmaf(fv, c2[j], iv * gv);
            float hn = ov * sigf(c2[j]);
            hwrf[((rg + 8 * j) * HSTR + hk) * 4 + 2 + hhalf] = hn;
            out[(size_t)(b0g + rg + 8 * j) * (T_ * H_) + t * H_ + h] = hn;
        }
        __syncthreads();
    }
}

// ---------------------------------------------------------------------------
extern "C" void kernel_launch(void* const* d_in, const int* in_sizes, int n_in,
                              void* d_out, int out_size)
{
    const float* x  = (const float*)d_in[0];
    const float* W1 = (const float*)d_in[1];
    const float* U1 = (const float*)d_in[2];
    const float* b1 = (const float*)d_in[3];
    const float* W2 = (const float*)d_in[4];
    const float* U2 = (const float*)d_in[5];
    const float* b2 = (const float*)d_in[6];
    float* out = (float*)d_out;

    xz1_gemm_kernel<<<(B_ * T_) / GR, 256>>>(x, W1, b1);

    cudaFuncSetAttribute(lstm_scan_kernel,
                         cudaFuncAttributeMaxDynamicSharedMemorySize, SCAN_SMEM);
    lstm_scan_kernel<<<B_ / BT, 512, SCAN_SMEM>>>(U1, W2, U2, b2, out);
}